// round 15
// baseline (speedup 1.0000x reference)
#include <cuda_runtime.h>
#include <cuda_fp16.h>
#include <math.h>
#include <stdint.h>

#define D_MODEL 512
#define DI      1024
#define ROWS    32768

// ---------------- scratch (device globals) ----------------
__device__ __half g_xn_hi[ROWS * D_MODEL];
__device__ __half g_xn_lo[ROWS * D_MODEL];
__device__ float g_u    [ROWS * DI];
__device__ float g_z    [ROWS * DI];
__device__ float g_uact [ROWS * DI];
__device__ __half g_ua_hi[ROWS * DI];
__device__ __half g_delta[ROWS * DI];
__device__ float g_hA   [ROWS * DI];
__device__ float g_hB   [ROWS * DI];
__device__ __half g_h_hi[ROWS * DI];
__device__ __half g_h_lo[ROWS * DI];
__device__ __half g_g_hi[ROWS * DI];
__device__ __half g_g_lo[ROWS * DI];
// transposed weights: [N][K] fp16
__device__ __half g_win_hi [2048 * 512];
__device__ __half g_wdt_hi [1024 * 1024];
__device__ __half g_wssm_hi[1024 * 1024];
__device__ __half g_wout_hi[512 * 1024];
// conv weights transposed to [tap][channel]
__device__ float g_clw_t[9 * DI];
__device__ float g_cdw_t[9 * DI];

// ---------------- small helpers ----------------
__device__ __forceinline__ float siluf(float v) { return v / (1.0f + expf(-v)); }
__device__ __forceinline__ float softplus_clamp(float v) {
    float sp = (v > 15.0f) ? v : log1pf(expf(v));
    return fminf(sp, 0.15f);
}
__device__ __forceinline__ void split2h(float v, __half& hi, __half& lo) {
    hi = __float2half_rn(v);
    lo = __float2half_rn(v - __half2float(hi));
}
__device__ __forceinline__ void fma4(float4& acc, const float4 wv, const float4 tv) {
    acc.x = fmaf(wv.x, tv.x, acc.x);
    acc.y = fmaf(wv.y, tv.y, acc.y);
    acc.z = fmaf(wv.z, tv.z, acc.z);
    acc.w = fmaf(wv.w, tv.w, acc.w);
}

__device__ __forceinline__ void cpasync16(uint32_t dst, const void* src) {
    asm volatile("cp.async.cg.shared.global [%0], [%1], 16;" :: "r"(dst), "l"(src));
}
__device__ __forceinline__ void ldsm4(uint32_t a, uint32_t& r0, uint32_t& r1,
                                      uint32_t& r2, uint32_t& r3) {
    asm volatile("ldmatrix.sync.aligned.m8n8.x4.shared.b16 {%0,%1,%2,%3}, [%4];"
                 : "=r"(r0), "=r"(r1), "=r"(r2), "=r"(r3) : "r"(a));
}
__device__ __forceinline__ void mma16816h(float* c, const uint32_t* a,
                                          uint32_t b0, uint32_t b1) {
    asm volatile(
        "mma.sync.aligned.m16n8k16.row.col.f32.f16.f16.f32 "
        "{%0,%1,%2,%3}, {%4,%5,%6,%7}, {%8,%9}, {%0,%1,%2,%3};"
        : "+f"(c[0]), "+f"(c[1]), "+f"(c[2]), "+f"(c[3])
        : "r"(a[0]), "r"(a[1]), "r"(a[2]), "r"(a[3]), "r"(b0), "r"(b1));
}

// ---------------- LayerNorm -> fp16 hi/lo split ----------------
__global__ void __launch_bounds__(256) ln_kernel(const float* __restrict__ x,
                                                 const float* __restrict__ gamma,
                                                 const float* __restrict__ beta) {
    int row = blockIdx.x;
    const float* xr = x + (size_t)row * D_MODEL;
    int t = threadIdx.x;
    float v0 = xr[t], v1 = xr[t + 256];
    float s = v0 + v1, sq = v0 * v0 + v1 * v1;
    __shared__ float sh[32], shq[32];
    #pragma unroll
    for (int o = 16; o; o >>= 1) {
        s  += __shfl_down_sync(0xffffffffu, s,  o);
        sq += __shfl_down_sync(0xffffffffu, sq, o);
    }
    int lane = t & 31, w = t >> 5;
    if (lane == 0) { sh[w] = s; shq[w] = sq; }
    __syncthreads();
    if (t == 0) {
        float ts = 0.f, tq = 0.f;
        #pragma unroll
        for (int i = 0; i < 8; i++) { ts += sh[i]; tq += shq[i]; }
        float mu = ts * (1.0f / D_MODEL);
        float var = tq * (1.0f / D_MODEL) - mu * mu;
        sh[0] = mu;
        shq[0] = rsqrtf(var + 1e-5f);
    }
    __syncthreads();
    float mu = sh[0], rs = shq[0];
    size_t o = (size_t)row * D_MODEL;
    float a = (v0 - mu) * rs * gamma[t] + beta[t];
    float b = (v1 - mu) * rs * gamma[t + 256] + beta[t + 256];
    __half hi, lo;
    split2h(a, hi, lo); g_xn_hi[o + t] = hi;       g_xn_lo[o + t] = lo;
    split2h(b, hi, lo); g_xn_hi[o + t + 256] = hi; g_xn_lo[o + t + 256] = lo;
}

// ---------------- weight transpose (fp16 hi only) ----------------
__device__ __forceinline__ void wprep_tile(const float* __restrict__ W,
                                           __half* __restrict__ Thi,
                                           int K, int N, int tile) {
    __shared__ float t[32][33];
    int ntiles = N >> 5;
    int n0 = (tile % ntiles) * 32, k0 = (tile / ntiles) * 32;
    int tx = threadIdx.x & 31, ty = threadIdx.x >> 5;
    #pragma unroll
    for (int dy = 0; dy < 32; dy += 8)
        t[ty + dy][tx] = W[(size_t)(k0 + ty + dy) * N + n0 + tx];
    __syncthreads();
    #pragma unroll
    for (int dy = 0; dy < 32; dy += 8) {
        size_t o = (size_t)(n0 + ty + dy) * K + k0 + tx;
        Thi[o] = __float2half_rn(t[tx][ty + dy]);
    }
}

__global__ void __launch_bounds__(256) wprep2_kernel(
        const float* __restrict__ W0, __half* __restrict__ T0h,
        int K0, int N0, int ntile0,
        const float* __restrict__ W1, __half* __restrict__ T1h,
        int K1, int N1) {
    int b = blockIdx.x;
    if (b < ntile0) wprep_tile(W0, T0h, K0, N0, b);
    else            wprep_tile(W1, T1h, K1, N1, b - ntile0);
}

// ---------------- conv weight transpose: [C][9] -> [9][C] ----------------
__global__ void __launch_bounds__(256) convw_prep(const float* __restrict__ wl,
                                                  const float* __restrict__ wd) {
    int o = blockIdx.x * 256 + threadIdx.x;
    int which = o >= 9 * DI;
    int oo = which ? o - 9 * DI : o;
    int t = oo / DI, c = oo % DI;
    float v = (which ? wd : wl)[c * 9 + t];
    (which ? g_cdw_t : g_clw_t)[oo] = v;
}

// ---------------- HMMA fp16 GEMM, 128x256x32 tiles, 3-stage, 512 threads ----
// NPROD: 1 = ah*bh; 2 = ah*bh + al*bh
#define ASZ_   10240u
#define BSZ_   20480u

template<int K, int NPROD>
__device__ __forceinline__ void load_stage(uint32_t st, int tid,
        const __half* __restrict__ Ahi, const __half* __restrict__ Alo,
        const __half* __restrict__ Bhi,
        size_t arow, size_t brow, int chunk) {
    constexpr uint32_t AORG = (NPROD >= 2 ? 2u : 1u) * ASZ_;
    {
        int r = tid >> 2, cb = (tid & 3) * 16;
        uint32_t sa = st + (uint32_t)(r * 80 + cb);
        size_t ga = (arow + r) * (size_t)(K * 2) + chunk * 64 + cb;
        cpasync16(sa, (const char*)Ahi + ga);
        if (NPROD >= 2) cpasync16(sa + ASZ_, (const char*)Alo + ga);
    }
    #pragma unroll
    for (int i = 0; i < 2; i++) {
        int idx = tid + i * 512;
        int r = idx >> 2, cb = (idx & 3) * 16;
        uint32_t sbm = st + AORG + (uint32_t)(r * 80 + cb);
        size_t gb = (brow + r) * (size_t)(K * 2) + chunk * 64 + cb;
        cpasync16(sbm, (const char*)Bhi + gb);
    }
    asm volatile("cp.async.commit_group;");
}

// MODE 0: in_proj -> g_u / g_z split at col DI
// MODE 1: delta (fp16); MODE 2: g epilogue; MODE 3: out + residual
template<int MODE, int NOUT, int K, int NPROD>
__global__ void __launch_bounds__(512, 1)
hmma_gemm(const __half* __restrict__ Ahi, const __half* __restrict__ Alo,
          const __half* __restrict__ Bhi,
          const float* __restrict__ p0, const float* __restrict__ res,
          float* __restrict__ outp) {
    constexpr uint32_t AORG = (NPROD >= 2 ? 2u : 1u) * ASZ_;
    constexpr uint32_t STG  = AORG + BSZ_;
    extern __shared__ char smem_raw[];
    uint32_t sb = (uint32_t)__cvta_generic_to_shared(smem_raw);
    const int tid = threadIdx.x;
    const int lane = tid & 31, wid = tid >> 5;
    const int wm = wid & 3, wn = wid >> 2;           // 4m x 4n, warp tile 32x64
    const int bx = blockIdx.x, by = blockIdx.y;
    const size_t arow = (size_t)by * 128;
    const size_t brow = (size_t)bx * 256;
    constexpr int NC = K / 32;

    const int a_r = (lane & 7) + ((lane >> 3) & 1) * 8;
    const int a_c = ((lane >> 4) & 1) * 8;
    const int b_r = (lane & 7) + ((lane >> 4) & 1) * 8;
    const int b_c = ((lane >> 3) & 1) * 8;
    const uint32_t a_off = (uint32_t)((wm * 32 + a_r) * 80 + a_c * 2);
    const uint32_t b_off = AORG + (uint32_t)((wn * 64 + b_r) * 80 + b_c * 2);

    load_stage<K, NPROD>(sb,       tid, Ahi, Alo, Bhi, arow, brow, 0);
    load_stage<K, NPROD>(sb + STG, tid, Ahi, Alo, Bhi, arow, brow, 1);

    float acc[2][8][4];
    #pragma unroll
    for (int i = 0; i < 2; i++)
        #pragma unroll
        for (int j = 0; j < 8; j++)
            #pragma unroll
            for (int q = 0; q < 4; q++) acc[i][j][q] = 0.f;

    #pragma unroll 1
    for (int i = 0; i < NC; i++) {
        if (i + 1 < NC) asm volatile("cp.async.wait_group 1;");
        else            asm volatile("cp.async.wait_group 0;");
        __syncthreads();
        if (i + 2 < NC) {
            uint32_t stw = sb + (uint32_t)((i + 2) % 3) * STG;
            load_stage<K, NPROD>(stw, tid, Ahi, Alo, Bhi, arow, brow, i + 2);
        }
        uint32_t st = sb + (uint32_t)(i % 3) * STG;
        #pragma unroll
        for (int ks = 0; ks < 2; ks++) {
            uint32_t kb = (uint32_t)(ks * 32);
            uint32_t ah[2][4], al[2][4];
            #pragma unroll
            for (int mt = 0; mt < 2; mt++) {
                uint32_t a = st + a_off + (uint32_t)(mt * 16 * 80) + kb;
                ldsm4(a, ah[mt][0], ah[mt][1], ah[mt][2], ah[mt][3]);
                if (NPROD >= 2) ldsm4(a + ASZ_, al[mt][0], al[mt][1], al[mt][2], al[mt][3]);
            }
            #pragma unroll
            for (int np = 0; np < 4; np++) {
                uint32_t b = st + b_off + (uint32_t)(np * 16 * 80) + kb;
                uint32_t bh[4];
                ldsm4(b, bh[0], bh[1], bh[2], bh[3]);
                #pragma unroll
                for (int mt = 0; mt < 2; mt++) {
                    #pragma unroll
                    for (int hh = 0; hh < 2; hh++) {
                        float* c = acc[mt][np * 2 + hh];
                        mma16816h(c, ah[mt], bh[hh * 2], bh[hh * 2 + 1]);
                        if (NPROD >= 2)
                            mma16816h(c, al[mt], bh[hh * 2], bh[hh * 2 + 1]);
                    }
                }
            }
        }
    }

    // ---- epilogue ----
    const int quad = lane >> 2, qi = lane & 3;
    #pragma unroll
    for (int mt = 0; mt < 2; mt++) {
        #pragma unroll
        for (int nt = 0; nt < 8; nt++) {
            int r0 = by * 128 + wm * 32 + mt * 16 + quad;
            int c  = bx * 256 + wn * 64 + nt * 8 + qi * 2;
            float* a = acc[mt][nt];
            #pragma unroll
            for (int half = 0; half < 2; half++) {
                int row = r0 + half * 8;
                float v0 = a[half * 2], v1 = a[half * 2 + 1];
                if (MODE == 0) {
                    float* dst = (c < DI) ? (g_u + (size_t)row * DI + c)
                                          : (g_z + (size_t)row * DI + (c - DI));
                    *(float2*)dst = make_float2(v0, v1);
                } else if (MODE == 1) {
                    float2 bb = *(const float2*)(p0 + c);
                    __half2 d2 = __floats2half2_rn(softplus_clamp(v0 + bb.x),
                                                   softplus_clamp(v1 + bb.y));
                    *(__half2*)(g_delta + (size_t)row * DI + c) = d2;
                } else if (MODE == 2) {
                    size_t o = (size_t)row * DI + c;
                    float2 uu = *(const float2*)(g_uact + o);
                    float2 zz = *(const float2*)(g_z + o);
                    float2 dp = *(const float2*)(p0 + c);
                    float w0 = (v0 + uu.x * dp.x) * siluf(zz.x);
                    float w1 = (v1 + uu.y * dp.y) * siluf(zz.y);
                    __half h0, l0, h1, l1;
                    split2h(w0, h0, l0);
                    split2h(w1, h1, l1);
                    *(__half2*)(g_g_hi + o) = __half2(h0, h1);
                    *(__half2*)(g_g_lo + o) = __half2(l0, l1);
                } else {
                    size_t o = (size_t)row * (size_t)NOUT + c;
                    float2 rr = *(const float2*)(res + o);
                    *(float2*)(outp + o) = make_float2(v0 + rr.x, v1 + rr.y);
                }
            }
        }
    }
}

// ---------------- conv kernels: 2y x 4x sliding window, 4 channels/thread ----
// unit: x0 = (u&15)*4, y0 = ((u>>4)&31)*2, b = u>>9  (4096 units)
__device__ __forceinline__ void load_row_zero(float4* dst, const float* __restrict__ src,
                                              int b, int yy, int x0, int c) {
    bool oky = (unsigned)yy < 64u;
    #pragma unroll
    for (int j = 0; j < 6; j++) {
        int xx = x0 + j - 1;
        bool ok = oky && ((unsigned)xx < 64u);
        int srow = (b << 12) | ((oky ? yy : 0) << 6) | (ok ? xx : 0);
        float4 v = *(const float4*)(src + (size_t)srow * DI + c);
        if (!ok) v = make_float4(0.f, 0.f, 0.f, 0.f);
        dst[j] = v;
    }
}
__device__ __forceinline__ void load_row_clamp(float4* dst, const float* __restrict__ src,
                                               int b, int yy, int x0, int c) {
    int yc = min(max(yy, 0), 63);
    #pragma unroll
    for (int j = 0; j < 6; j++) {
        int xx = min(max(x0 + j - 1, 0), 63);
        int srow = (b << 12) | (yc << 6) | xx;
        dst[j] = *(const float4*)(src + (size_t)srow * DI + c);
    }
}

__global__ void __launch_bounds__(256) conv_local_x8(const float* __restrict__ bias) {
    int idx = blockIdx.x * 256 + threadIdx.x;
    int c4 = idx & 255;
    int unit = idx >> 8;
    int x0 = (unit & 15) * 4;
    int y0 = ((unit >> 4) & 31) * 2;
    int b  = unit >> 9;
    int c  = c4 * 4;

    float4 tv[3][6];
    load_row_zero(tv[0], g_u, b, y0 - 1, x0, c);
    load_row_zero(tv[1], g_u, b, y0,     x0, c);
    load_row_zero(tv[2], g_u, b, y0 + 1, x0, c);
    float4 wt[9];
    #pragma unroll
    for (int t = 0; t < 9; t++) wt[t] = *(const float4*)(g_clw_t + t * DI + c);
    float4 bv = *(const float4*)(bias + c);

    #pragma unroll
    for (int ystep = 0; ystep < 2; ystep++) {
        int r0 = ystep;              // ky=0 row index in tv
        int r1 = (ystep + 1) % 3;    // ky=1
        int r2 = (ystep + 2) % 3;    // ky=2
        int yout = y0 + ystep;
        #pragma unroll
        for (int px = 0; px < 4; px++) {
            float4 acc = bv;
            #pragma unroll
            for (int kx = 0; kx < 3; kx++) {
                fma4(acc, wt[kx],     tv[r0][px + kx]);
                fma4(acc, wt[3 + kx], tv[r1][px + kx]);
                fma4(acc, wt[6 + kx], tv[r2][px + kx]);
            }
            float4 v = make_float4(siluf(acc.x), siluf(acc.y), siluf(acc.z), siluf(acc.w));
            size_t o = ((size_t)((b << 12) | (yout << 6) | (x0 + px))) * DI + c;
            *(float4*)(g_uact + o) = v;
            __half2 h01 = __floats2half2_rn(v.x, v.y);
            __half2 h23 = __floats2half2_rn(v.z, v.w);
            *(uint2*)(g_ua_hi + o) = make_uint2(*(uint32_t*)&h01, *(uint32_t*)&h23);
        }
        if (ystep == 0) load_row_zero(tv[0], g_u, b, y0 + 2, x0, c);
    }
}

template<bool LAST>
__global__ void __launch_bounds__(256) conv_diff_x8(const float* __restrict__ hin,
                                                    float* __restrict__ hout,
                                                    const float* __restrict__ alpha,
                                                    const float* __restrict__ beta) {
    int idx = blockIdx.x * 256 + threadIdx.x;
    int c4 = idx & 255;
    int unit = idx >> 8;
    int x0 = (unit & 15) * 4;
    int y0 = ((unit >> 4) & 31) * 2;
    int b  = unit >> 9;
    int c  = c4 * 4;

    float4 tv[3][6];
    load_row_clamp(tv[0], hin, b, y0 - 1, x0, c);
    load_row_clamp(tv[1], hin, b, y0,     x0, c);
    load_row_clamp(tv[2], hin, b, y0 + 1, x0, c);
    float4 wt[9];
    #pragma unroll
    for (int t = 0; t < 9; t++) wt[t] = *(const float4*)(g_cdw_t + t * DI + c);
    float4 al = *(const float4*)(alpha + c);
    float4 be = *(const float4*)(beta + c);

    #pragma unroll
    for (int ystep = 0; ystep < 2; ystep++) {
        int r0 = ystep;
        int r1 = (ystep + 1) % 3;
        int r2 = (ystep + 2) % 3;
        int yout = y0 + ystep;
        #pragma unroll
        for (int px = 0; px < 4; px++) {
            float4 acc = make_float4(0.f, 0.f, 0.f, 0.f);
            #pragma unroll
            for (int kx = 0; kx < 3; kx++) {
                fma4(acc, wt[kx],     tv[r0][px + kx]);
                fma4(acc, wt[3 + kx], tv[r1][px + kx]);
                fma4(acc, wt[6 + kx], tv[r2][px + kx]);
            }
            size_t o = ((size_t)((b << 12) | (yout << 6) | (x0 + px))) * DI + c;
            float4 h = tv[r1][px + 1];
            uint2 draw = *(const uint2*)(g_delta + o);
            float2 d01 = __half22float2(*(__half2*)&draw.x);
            float2 d23 = __half22float2(*(__half2*)&draw.y);
            float4 v;
            v.x = h.x + 0.25f * (d01.x * acc.x + al.x * h.x - be.x * h.x * h.x * h.x);
            v.y = h.y + 0.25f * (d01.y * acc.y + al.y * h.y - be.y * h.y * h.y * h.y);
            v.z = h.z + 0.25f * (d23.x * acc.z + al.z * h.z - be.z * h.z * h.z * h.z);
            v.w = h.w + 0.25f * (d23.y * acc.w + al.w * h.w - be.w * h.w * h.w * h.w);
            if (LAST) {
                __half h0, l0, h1, l1, h2, l2, h3, l3;
                split2h(v.x, h0, l0); split2h(v.y, h1, l1);
                split2h(v.z, h2, l2); split2h(v.w, h3, l3);
                __half2 hh01(h0, h1), hh23(h2, h3), ll01(l0, l1), ll23(l2, l3);
                *(uint2*)(g_h_hi + o) = make_uint2(*(uint32_t*)&hh01, *(uint32_t*)&hh23);
                *(uint2*)(g_h_lo + o) = make_uint2(*(uint32_t*)&ll01, *(uint32_t*)&ll23);
            } else {
                *(float4*)(hout + o) = v;
            }
        }
        if (ystep == 0) load_row_clamp(tv[0], hin, b, y0 + 2, x0, c);
    }
}

extern "C" void kernel_launch(void* const* d_in, const int* in_sizes, int n_in,
                              void* d_out, int out_size) {
    const float* x         = (const float*)d_in[0];
    const float* ln_gamma  = (const float*)d_in[1];
    const float* ln_beta   = (const float*)d_in[2];
    const float* W_in      = (const float*)d_in[3];
    const float* conv_lw   = (const float*)d_in[4];
    const float* conv_lb   = (const float*)d_in[5];
    const float* W_dt      = (const float*)d_in[6];
    const float* b_dt      = (const float*)d_in[7];
    const float* D_param   = (const float*)d_in[8];
    const float* conv_dw   = (const float*)d_in[9];
    const float* alpha     = (const float*)d_in[10];
    const float* beta_r    = (const float*)d_in[11];
    const float* W_ssm_out = (const float*)d_in[12];
    const float* W_out     = (const float*)d_in[13];
    float* out             = (float*)d_out;

    __half *xn_hi, *xn_lo, *ua_hi, *h_hi, *h_lo, *gg_hi, *gg_lo;
    __half *win_hi, *wdt_hi, *wssm_hi, *wout_hi;
    float *hA, *hB, *uact;
    cudaGetSymbolAddress((void**)&xn_hi, g_xn_hi);
    cudaGetSymbolAddress((void**)&xn_lo, g_xn_lo);
    cudaGetSymbolAddress((void**)&ua_hi, g_ua_hi);
    cudaGetSymbolAddress((void**)&h_hi,  g_h_hi);
    cudaGetSymbolAddress((void**)&h_lo,  g_h_lo);
    cudaGetSymbolAddress((void**)&gg_hi, g_g_hi);
    cudaGetSymbolAddress((void**)&gg_lo, g_g_lo);
    cudaGetSymbolAddress((void**)&win_hi,  g_win_hi);
    cudaGetSymbolAddress((void**)&wdt_hi,  g_wdt_hi);
    cudaGetSymbolAddress((void**)&wssm_hi, g_wssm_hi);
    cudaGetSymbolAddress((void**)&wout_hi, g_wout_hi);
    cudaGetSymbolAddress((void**)&hA,   g_hA);
    cudaGetSymbolAddress((void**)&hB,   g_hB);
    cudaGetSymbolAddress((void**)&uact, g_uact);

    const int SM2 = 3 * (2 * 10240 + 20480);      // 122880 (2-prod)
    const int SM1 = 3 * (10240 + 20480);          // 92160  (1-prod)
    cudaFuncSetAttribute((const void*)hmma_gemm<0, 2048, 512,  2>,
                         cudaFuncAttributeMaxDynamicSharedMemorySize, SM2);
    cudaFuncSetAttribute((const void*)hmma_gemm<1, 1024, 1024, 1>,
                         cudaFuncAttributeMaxDynamicSharedMemorySize, SM1);
    cudaFuncSetAttribute((const void*)hmma_gemm<2, 1024, 1024, 2>,
                         cudaFuncAttributeMaxDynamicSharedMemorySize, SM2);
    cudaFuncSetAttribute((const void*)hmma_gemm<3, 512,  1024, 2>,
                         cudaFuncAttributeMaxDynamicSharedMemorySize, SM2);

    const int EWX8_BLOCKS = (ROWS * DI / 32) / 256;   // 4096

    // 0) weight transpose (fp16 hi) + conv weight transpose
    wprep2_kernel<<<2048, 256>>>(W_in, win_hi, 512, 2048, 1024,
                                 W_dt, wdt_hi, 1024, 1024);
    wprep2_kernel<<<1536, 256>>>(W_ssm_out, wssm_hi, 1024, 1024, 1024,
                                 W_out, wout_hi, 1024, 512);
    convw_prep<<<(2 * 9 * DI) / 256, 256>>>(conv_lw, conv_dw);

    // 1) LayerNorm -> xn hi/lo
    ln_kernel<<<ROWS, 256>>>(x, ln_gamma, ln_beta);

    // 2) in_proj -> u / z   [2-product]
    hmma_gemm<0, 2048, 512, 2><<<dim3(8, ROWS / 128), 512, SM2>>>(
        xn_hi, xn_lo, win_hi, nullptr, nullptr, nullptr);

    // 3) local conv + SiLU -> uact (fp32 + fp16 hi)
    conv_local_x8<<<EWX8_BLOCKS, 256>>>(conv_lb);

    // 4) delta (fp16)   [1-product]
    hmma_gemm<1, 1024, 1024, 1><<<dim3(4, ROWS / 128), 512, SM1>>>(
        ua_hi, nullptr, wdt_hi, b_dt, nullptr, nullptr);

    // 5) Euler x4 (last writes h hi/lo)
    conv_diff_x8<false><<<EWX8_BLOCKS, 256>>>(uact, hA, alpha, beta_r);
    conv_diff_x8<false><<<EWX8_BLOCKS, 256>>>(hA,   hB, alpha, beta_r);
    conv_diff_x8<false><<<EWX8_BLOCKS, 256>>>(hB,   hA, alpha, beta_r);
    conv_diff_x8<true ><<<EWX8_BLOCKS, 256>>>(hA, nullptr, alpha, beta_r);

    // 6) g = (h@Wssm + u*D) * silu(z) -> g hi/lo   [2-product]
    hmma_gemm<2, 1024, 1024, 2><<<dim3(4, ROWS / 128), 512, SM2>>>(
        h_hi, h_lo, wssm_hi, D_param, nullptr, nullptr);

    // 7) out = g@Wout + residual   [2-product]
    hmma_gemm<3, 512, 1024, 2><<<dim3(2, ROWS / 128), 512, SM2>>>(
        gg_hi, gg_lo, wout_hi, nullptr, x, out);
}

// round 16
// speedup vs baseline: 1.0073x; 1.0073x over previous
#include <cuda_runtime.h>
#include <cuda_fp16.h>
#include <math.h>
#include <stdint.h>

#define D_MODEL 512
#define DI      1024
#define ROWS    32768

// ---------------- scratch (device globals) ----------------
__device__ __half g_xn_hi[ROWS * D_MODEL];
__device__ __half g_xn_lo[ROWS * D_MODEL];
__device__ float g_u    [ROWS * DI];
__device__ float g_z    [ROWS * DI];
__device__ float g_uact [ROWS * DI];
__device__ __half g_ua_hi[ROWS * DI];
__device__ __half g_delta[ROWS * DI];
__device__ float g_hA   [ROWS * DI];
__device__ float g_hB   [ROWS * DI];
__device__ __half g_h_hi[ROWS * DI];
__device__ __half g_h_lo[ROWS * DI];
__device__ __half g_g_hi[ROWS * DI];
__device__ __half g_g_lo[ROWS * DI];
// transposed weights: [N][K] fp16
__device__ __half g_win_hi [2048 * 512];
__device__ __half g_wdt_hi [1024 * 1024];
__device__ __half g_wssm_hi[1024 * 1024];
__device__ __half g_wout_hi[512 * 1024];
// conv weights transposed to [tap][channel]
__device__ float g_clw_t[9 * DI];
__device__ float g_cdw_t[9 * DI];

// ---------------- small helpers ----------------
__device__ __forceinline__ float siluf(float v) { return v / (1.0f + expf(-v)); }
__device__ __forceinline__ float softplus_clamp(float v) {
    float sp = (v > 15.0f) ? v : log1pf(expf(v));
    return fminf(sp, 0.15f);
}
__device__ __forceinline__ void split2h(float v, __half& hi, __half& lo) {
    hi = __float2half_rn(v);
    lo = __float2half_rn(v - __half2float(hi));
}

__device__ __forceinline__ void cpasync16(uint32_t dst, const void* src) {
    asm volatile("cp.async.cg.shared.global [%0], [%1], 16;" :: "r"(dst), "l"(src));
}
__device__ __forceinline__ void ldsm4(uint32_t a, uint32_t& r0, uint32_t& r1,
                                      uint32_t& r2, uint32_t& r3) {
    asm volatile("ldmatrix.sync.aligned.m8n8.x4.shared.b16 {%0,%1,%2,%3}, [%4];"
                 : "=r"(r0), "=r"(r1), "=r"(r2), "=r"(r3) : "r"(a));
}
__device__ __forceinline__ void mma16816h(float* c, const uint32_t* a,
                                          uint32_t b0, uint32_t b1) {
    asm volatile(
        "mma.sync.aligned.m16n8k16.row.col.f32.f16.f16.f32 "
        "{%0,%1,%2,%3}, {%4,%5,%6,%7}, {%8,%9}, {%0,%1,%2,%3};"
        : "+f"(c[0]), "+f"(c[1]), "+f"(c[2]), "+f"(c[3])
        : "r"(a[0]), "r"(a[1]), "r"(a[2]), "r"(a[3]), "r"(b0), "r"(b1));
}

// ---------------- LayerNorm -> fp16 hi/lo split ----------------
__global__ void __launch_bounds__(256) ln_kernel(const float* __restrict__ x,
                                                 const float* __restrict__ gamma,
                                                 const float* __restrict__ beta) {
    int row = blockIdx.x;
    const float* xr = x + (size_t)row * D_MODEL;
    int t = threadIdx.x;
    float v0 = xr[t], v1 = xr[t + 256];
    float s = v0 + v1, sq = v0 * v0 + v1 * v1;
    __shared__ float sh[32], shq[32];
    #pragma unroll
    for (int o = 16; o; o >>= 1) {
        s  += __shfl_down_sync(0xffffffffu, s,  o);
        sq += __shfl_down_sync(0xffffffffu, sq, o);
    }
    int lane = t & 31, w = t >> 5;
    if (lane == 0) { sh[w] = s; shq[w] = sq; }
    __syncthreads();
    if (t == 0) {
        float ts = 0.f, tq = 0.f;
        #pragma unroll
        for (int i = 0; i < 8; i++) { ts += sh[i]; tq += shq[i]; }
        float mu = ts * (1.0f / D_MODEL);
        float var = tq * (1.0f / D_MODEL) - mu * mu;
        sh[0] = mu;
        shq[0] = rsqrtf(var + 1e-5f);
    }
    __syncthreads();
    float mu = sh[0], rs = shq[0];
    size_t o = (size_t)row * D_MODEL;
    float a = (v0 - mu) * rs * gamma[t] + beta[t];
    float b = (v1 - mu) * rs * gamma[t + 256] + beta[t + 256];
    __half hi, lo;
    split2h(a, hi, lo); g_xn_hi[o + t] = hi;       g_xn_lo[o + t] = lo;
    split2h(b, hi, lo); g_xn_hi[o + t + 256] = hi; g_xn_lo[o + t + 256] = lo;
}

// ---------------- weight transpose (fp16 hi only) ----------------
__device__ __forceinline__ void wprep_tile(const float* __restrict__ W,
                                           __half* __restrict__ Thi,
                                           int K, int N, int tile) {
    __shared__ float t[32][33];
    int ntiles = N >> 5;
    int n0 = (tile % ntiles) * 32, k0 = (tile / ntiles) * 32;
    int tx = threadIdx.x & 31, ty = threadIdx.x >> 5;
    #pragma unroll
    for (int dy = 0; dy < 32; dy += 8)
        t[ty + dy][tx] = W[(size_t)(k0 + ty + dy) * N + n0 + tx];
    __syncthreads();
    #pragma unroll
    for (int dy = 0; dy < 32; dy += 8) {
        size_t o = (size_t)(n0 + ty + dy) * K + k0 + tx;
        Thi[o] = __float2half_rn(t[tx][ty + dy]);
    }
}

__global__ void __launch_bounds__(256) wprep2_kernel(
        const float* __restrict__ W0, __half* __restrict__ T0h,
        int K0, int N0, int ntile0,
        const float* __restrict__ W1, __half* __restrict__ T1h,
        int K1, int N1) {
    int b = blockIdx.x;
    if (b < ntile0) wprep_tile(W0, T0h, K0, N0, b);
    else            wprep_tile(W1, T1h, K1, N1, b - ntile0);
}

// ---------------- conv weight transpose: [C][9] -> [9][C] ----------------
__global__ void __launch_bounds__(256) convw_prep(const float* __restrict__ wl,
                                                  const float* __restrict__ wd) {
    int o = blockIdx.x * 256 + threadIdx.x;
    int which = o >= 9 * DI;
    int oo = which ? o - 9 * DI : o;
    int t = oo / DI, c = oo % DI;
    float v = (which ? wd : wl)[c * 9 + t];
    (which ? g_cdw_t : g_clw_t)[oo] = v;
}

// ---------------- HMMA fp16 GEMM, 128x256x32 tiles, 3-stage, 512 threads ----
// NPROD: 1 = ah*bh; 2 = ah*bh + al*bh
#define ASZ_   10240u
#define BSZ_   20480u

template<int K, int NPROD>
__device__ __forceinline__ void load_stage(uint32_t st, int tid,
        const __half* __restrict__ Ahi, const __half* __restrict__ Alo,
        const __half* __restrict__ Bhi,
        size_t arow, size_t brow, int chunk) {
    constexpr uint32_t AORG = (NPROD >= 2 ? 2u : 1u) * ASZ_;
    {
        int r = tid >> 2, cb = (tid & 3) * 16;
        uint32_t sa = st + (uint32_t)(r * 80 + cb);
        size_t ga = (arow + r) * (size_t)(K * 2) + chunk * 64 + cb;
        cpasync16(sa, (const char*)Ahi + ga);
        if (NPROD >= 2) cpasync16(sa + ASZ_, (const char*)Alo + ga);
    }
    #pragma unroll
    for (int i = 0; i < 2; i++) {
        int idx = tid + i * 512;
        int r = idx >> 2, cb = (idx & 3) * 16;
        uint32_t sbm = st + AORG + (uint32_t)(r * 80 + cb);
        size_t gb = (brow + r) * (size_t)(K * 2) + chunk * 64 + cb;
        cpasync16(sbm, (const char*)Bhi + gb);
    }
    asm volatile("cp.async.commit_group;");
}

// MODE 0: in_proj -> g_u / g_z split at col DI
// MODE 1: delta (fp16); MODE 2: g epilogue; MODE 3: out + residual
template<int MODE, int NOUT, int K, int NPROD>
__global__ void __launch_bounds__(512, 1)
hmma_gemm(const __half* __restrict__ Ahi, const __half* __restrict__ Alo,
          const __half* __restrict__ Bhi,
          const float* __restrict__ p0, const float* __restrict__ res,
          float* __restrict__ outp) {
    constexpr uint32_t AORG = (NPROD >= 2 ? 2u : 1u) * ASZ_;
    constexpr uint32_t STG  = AORG + BSZ_;
    extern __shared__ char smem_raw[];
    uint32_t sb = (uint32_t)__cvta_generic_to_shared(smem_raw);
    const int tid = threadIdx.x;
    const int lane = tid & 31, wid = tid >> 5;
    const int wm = wid & 3, wn = wid >> 2;           // 4m x 4n, warp tile 32x64
    const int bx = blockIdx.x, by = blockIdx.y;
    const size_t arow = (size_t)by * 128;
    const size_t brow = (size_t)bx * 256;
    constexpr int NC = K / 32;

    const int a_r = (lane & 7) + ((lane >> 3) & 1) * 8;
    const int a_c = ((lane >> 4) & 1) * 8;
    const int b_r = (lane & 7) + ((lane >> 4) & 1) * 8;
    const int b_c = ((lane >> 3) & 1) * 8;
    const uint32_t a_off = (uint32_t)((wm * 32 + a_r) * 80 + a_c * 2);
    const uint32_t b_off = AORG + (uint32_t)((wn * 64 + b_r) * 80 + b_c * 2);

    load_stage<K, NPROD>(sb,       tid, Ahi, Alo, Bhi, arow, brow, 0);
    load_stage<K, NPROD>(sb + STG, tid, Ahi, Alo, Bhi, arow, brow, 1);

    float acc[2][8][4];
    #pragma unroll
    for (int i = 0; i < 2; i++)
        #pragma unroll
        for (int j = 0; j < 8; j++)
            #pragma unroll
            for (int q = 0; q < 4; q++) acc[i][j][q] = 0.f;

    #pragma unroll 1
    for (int i = 0; i < NC; i++) {
        if (i + 1 < NC) asm volatile("cp.async.wait_group 1;");
        else            asm volatile("cp.async.wait_group 0;");
        __syncthreads();
        if (i + 2 < NC) {
            uint32_t stw = sb + (uint32_t)((i + 2) % 3) * STG;
            load_stage<K, NPROD>(stw, tid, Ahi, Alo, Bhi, arow, brow, i + 2);
        }
        uint32_t st = sb + (uint32_t)(i % 3) * STG;
        #pragma unroll
        for (int ks = 0; ks < 2; ks++) {
            uint32_t kb = (uint32_t)(ks * 32);
            uint32_t ah[2][4], al[2][4];
            #pragma unroll
            for (int mt = 0; mt < 2; mt++) {
                uint32_t a = st + a_off + (uint32_t)(mt * 16 * 80) + kb;
                ldsm4(a, ah[mt][0], ah[mt][1], ah[mt][2], ah[mt][3]);
                if (NPROD >= 2) ldsm4(a + ASZ_, al[mt][0], al[mt][1], al[mt][2], al[mt][3]);
            }
            #pragma unroll
            for (int np = 0; np < 4; np++) {
                uint32_t b = st + b_off + (uint32_t)(np * 16 * 80) + kb;
                uint32_t bh[4];
                ldsm4(b, bh[0], bh[1], bh[2], bh[3]);
                #pragma unroll
                for (int mt = 0; mt < 2; mt++) {
                    #pragma unroll
                    for (int hh = 0; hh < 2; hh++) {
                        float* c = acc[mt][np * 2 + hh];
                        mma16816h(c, ah[mt], bh[hh * 2], bh[hh * 2 + 1]);
                        if (NPROD >= 2)
                            mma16816h(c, al[mt], bh[hh * 2], bh[hh * 2 + 1]);
                    }
                }
            }
        }
    }

    // ---- epilogue ----
    const int quad = lane >> 2, qi = lane & 3;
    #pragma unroll
    for (int mt = 0; mt < 2; mt++) {
        #pragma unroll
        for (int nt = 0; nt < 8; nt++) {
            int r0 = by * 128 + wm * 32 + mt * 16 + quad;
            int c  = bx * 256 + wn * 64 + nt * 8 + qi * 2;
            float* a = acc[mt][nt];
            #pragma unroll
            for (int half = 0; half < 2; half++) {
                int row = r0 + half * 8;
                float v0 = a[half * 2], v1 = a[half * 2 + 1];
                if (MODE == 0) {
                    float* dst = (c < DI) ? (g_u + (size_t)row * DI + c)
                                          : (g_z + (size_t)row * DI + (c - DI));
                    *(float2*)dst = make_float2(v0, v1);
                } else if (MODE == 1) {
                    float2 bb = *(const float2*)(p0 + c);
                    __half2 d2 = __floats2half2_rn(softplus_clamp(v0 + bb.x),
                                                   softplus_clamp(v1 + bb.y));
                    *(__half2*)(g_delta + (size_t)row * DI + c) = d2;
                } else if (MODE == 2) {
                    size_t o = (size_t)row * DI + c;
                    float2 uu = *(const float2*)(g_uact + o);
                    float2 zz = *(const float2*)(g_z + o);
                    float2 dp = *(const float2*)(p0 + c);
                    float w0 = (v0 + uu.x * dp.x) * siluf(zz.x);
                    float w1 = (v1 + uu.y * dp.y) * siluf(zz.y);
                    __half h0, l0, h1, l1;
                    split2h(w0, h0, l0);
                    split2h(w1, h1, l1);
                    *(__half2*)(g_g_hi + o) = __half2(h0, h1);
                    *(__half2*)(g_g_lo + o) = __half2(l0, l1);
                } else {
                    size_t o = (size_t)row * (size_t)NOUT + c;
                    float2 rr = *(const float2*)(res + o);
                    *(float2*)(outp + o) = make_float2(v0 + rr.x, v1 + rr.y);
                }
            }
        }
    }
}

// ---------------- local conv (zero pad) + bias + SiLU, 4 x-pixels/thread ----
__global__ void __launch_bounds__(256) conv_local_x4(const float* __restrict__ bias) {
    int idx = blockIdx.x * 256 + threadIdx.x;          // over ROWS*DI/16
    int c4 = idx & 255;
    int unit = idx >> 8;                                // 8192 units
    int x0 = (unit & 15) * 4;
    int y  = (unit >> 4) & 63;
    int b  = unit >> 10;
    int c  = c4 * 4;

    float4 tv[3][6];
    #pragma unroll
    for (int ky = 0; ky < 3; ky++) {
        int yy = y + ky - 1;
        bool oky = (unsigned)yy < 64u;
        #pragma unroll
        for (int j = 0; j < 6; j++) {
            int xx = x0 + j - 1;
            bool ok = oky && ((unsigned)xx < 64u);
            int srow = (b << 12) | ((oky ? yy : 0) << 6) | (ok ? xx : 0);
            float4 v = *(const float4*)(g_u + (size_t)srow * DI + c);
            if (!ok) v = make_float4(0.f, 0.f, 0.f, 0.f);
            tv[ky][j] = v;
        }
    }
    float4 wt[9];
    #pragma unroll
    for (int t = 0; t < 9; t++) wt[t] = *(const float4*)(g_clw_t + t * DI + c);
    float4 bv = *(const float4*)(bias + c);

    #pragma unroll
    for (int px = 0; px < 4; px++) {
        float4 acc = bv;
        #pragma unroll
        for (int ky = 0; ky < 3; ky++)
            #pragma unroll
            for (int kx = 0; kx < 3; kx++) {
                float4 w = wt[ky * 3 + kx];
                float4 t = tv[ky][px + kx];
                acc.x = fmaf(w.x, t.x, acc.x);
                acc.y = fmaf(w.y, t.y, acc.y);
                acc.z = fmaf(w.z, t.z, acc.z);
                acc.w = fmaf(w.w, t.w, acc.w);
            }
        float4 v = make_float4(siluf(acc.x), siluf(acc.y), siluf(acc.z), siluf(acc.w));
        size_t o = ((size_t)((b << 12) | (y << 6) | (x0 + px))) * DI + c;
        *(float4*)(g_uact + o) = v;
        __half2 h01 = __floats2half2_rn(v.x, v.y);
        __half2 h23 = __floats2half2_rn(v.z, v.w);
        *(uint2*)(g_ua_hi + o) = make_uint2(*(uint32_t*)&h01, *(uint32_t*)&h23);
    }
}

// ---------------- diff conv (replicate pad) + Euler, 4 x-pixels/thread ----
template<bool LAST>
__global__ void __launch_bounds__(256) conv_diff_x4(const float* __restrict__ hin,
                                                    float* __restrict__ hout,
                                                    const float* __restrict__ alpha,
                                                    const float* __restrict__ beta) {
    int idx = blockIdx.x * 256 + threadIdx.x;
    int c4 = idx & 255;
    int unit = idx >> 8;
    int x0 = (unit & 15) * 4;
    int y  = (unit >> 4) & 63;
    int b  = unit >> 10;
    int c  = c4 * 4;

    float4 tv[3][6];
    #pragma unroll
    for (int ky = 0; ky < 3; ky++) {
        int yy = min(max(y + ky - 1, 0), 63);
        #pragma unroll
        for (int j = 0; j < 6; j++) {
            int xx = min(max(x0 + j - 1, 0), 63);
            int srow = (b << 12) | (yy << 6) | xx;
            tv[ky][j] = *(const float4*)(hin + (size_t)srow * DI + c);
        }
    }
    float4 wt[9];
    #pragma unroll
    for (int t = 0; t < 9; t++) wt[t] = *(const float4*)(g_cdw_t + t * DI + c);
    float4 al = *(const float4*)(alpha + c);
    float4 be = *(const float4*)(beta + c);

    #pragma unroll
    for (int px = 0; px < 4; px++) {
        float4 acc = make_float4(0.f, 0.f, 0.f, 0.f);
        #pragma unroll
        for (int ky = 0; ky < 3; ky++)
            #pragma unroll
            for (int kx = 0; kx < 3; kx++) {
                float4 w = wt[ky * 3 + kx];
                float4 t = tv[ky][px + kx];
                acc.x = fmaf(w.x, t.x, acc.x);
                acc.y = fmaf(w.y, t.y, acc.y);
                acc.z = fmaf(w.z, t.z, acc.z);
                acc.w = fmaf(w.w, t.w, acc.w);
            }
        size_t o = ((size_t)((b << 12) | (y << 6) | (x0 + px))) * DI + c;
        float4 h = tv[1][px + 1];
        uint2 draw = *(const uint2*)(g_delta + o);
        float2 d01 = __half22float2(*(__half2*)&draw.x);
        float2 d23 = __half22float2(*(__half2*)&draw.y);
        float4 v;
        v.x = h.x + 0.25f * (d01.x * acc.x + al.x * h.x - be.x * h.x * h.x * h.x);
        v.y = h.y + 0.25f * (d01.y * acc.y + al.y * h.y - be.y * h.y * h.y * h.y);
        v.z = h.z + 0.25f * (d23.x * acc.z + al.z * h.z - be.z * h.z * h.z * h.z);
        v.w = h.w + 0.25f * (d23.y * acc.w + al.w * h.w - be.w * h.w * h.w * h.w);
        if (LAST) {
            __half h0, l0, h1, l1, h2, l2, h3, l3;
            split2h(v.x, h0, l0); split2h(v.y, h1, l1);
            split2h(v.z, h2, l2); split2h(v.w, h3, l3);
            __half2 hh01(h0, h1), hh23(h2, h3), ll01(l0, l1), ll23(l2, l3);
            *(uint2*)(g_h_hi + o) = make_uint2(*(uint32_t*)&hh01, *(uint32_t*)&hh23);
            *(uint2*)(g_h_lo + o) = make_uint2(*(uint32_t*)&ll01, *(uint32_t*)&ll23);
        } else {
            *(float4*)(hout + o) = v;
        }
    }
}

extern "C" void kernel_launch(void* const* d_in, const int* in_sizes, int n_in,
                              void* d_out, int out_size) {
    const float* x         = (const float*)d_in[0];
    const float* ln_gamma  = (const float*)d_in[1];
    const float* ln_beta   = (const float*)d_in[2];
    const float* W_in      = (const float*)d_in[3];
    const float* conv_lw   = (const float*)d_in[4];
    const float* conv_lb   = (const float*)d_in[5];
    const float* W_dt      = (const float*)d_in[6];
    const float* b_dt      = (const float*)d_in[7];
    const float* D_param   = (const float*)d_in[8];
    const float* conv_dw   = (const float*)d_in[9];
    const float* alpha     = (const float*)d_in[10];
    const float* beta_r    = (const float*)d_in[11];
    const float* W_ssm_out = (const float*)d_in[12];
    const float* W_out     = (const float*)d_in[13];
    float* out             = (float*)d_out;

    __half *xn_hi, *xn_lo, *ua_hi, *h_hi, *h_lo, *gg_hi, *gg_lo;
    __half *win_hi, *wdt_hi, *wssm_hi, *wout_hi;
    float *hA, *hB, *uact;
    cudaGetSymbolAddress((void**)&xn_hi, g_xn_hi);
    cudaGetSymbolAddress((void**)&xn_lo, g_xn_lo);
    cudaGetSymbolAddress((void**)&ua_hi, g_ua_hi);
    cudaGetSymbolAddress((void**)&h_hi,  g_h_hi);
    cudaGetSymbolAddress((void**)&h_lo,  g_h_lo);
    cudaGetSymbolAddress((void**)&gg_hi, g_g_hi);
    cudaGetSymbolAddress((void**)&gg_lo, g_g_lo);
    cudaGetSymbolAddress((void**)&win_hi,  g_win_hi);
    cudaGetSymbolAddress((void**)&wdt_hi,  g_wdt_hi);
    cudaGetSymbolAddress((void**)&wssm_hi, g_wssm_hi);
    cudaGetSymbolAddress((void**)&wout_hi, g_wout_hi);
    cudaGetSymbolAddress((void**)&hA,   g_hA);
    cudaGetSymbolAddress((void**)&hB,   g_hB);
    cudaGetSymbolAddress((void**)&uact, g_uact);

    const int SM2 = 3 * (2 * 10240 + 20480);      // 122880 (2-prod)
    const int SM1 = 3 * (10240 + 20480);          // 92160  (1-prod)
    cudaFuncSetAttribute((const void*)hmma_gemm<0, 2048, 512,  2>,
                         cudaFuncAttributeMaxDynamicSharedMemorySize, SM2);
    cudaFuncSetAttribute((const void*)hmma_gemm<1, 1024, 1024, 1>,
                         cudaFuncAttributeMaxDynamicSharedMemorySize, SM1);
    cudaFuncSetAttribute((const void*)hmma_gemm<2, 1024, 1024, 2>,
                         cudaFuncAttributeMaxDynamicSharedMemorySize, SM2);
    cudaFuncSetAttribute((const void*)hmma_gemm<3, 512,  1024, 2>,
                         cudaFuncAttributeMaxDynamicSharedMemorySize, SM2);

    const int EWX4_BLOCKS = (ROWS * DI / 16) / 256;   // 8192

    // 0) weight transpose (fp16 hi) + conv weight transpose
    wprep2_kernel<<<2048, 256>>>(W_in, win_hi, 512, 2048, 1024,
                                 W_dt, wdt_hi, 1024, 1024);
    wprep2_kernel<<<1536, 256>>>(W_ssm_out, wssm_hi, 1024, 1024, 1024,
                                 W_out, wout_hi, 1024, 512);
    convw_prep<<<(2 * 9 * DI) / 256, 256>>>(conv_lw, conv_dw);

    // 1) LayerNorm -> xn hi/lo
    ln_kernel<<<ROWS, 256>>>(x, ln_gamma, ln_beta);

    // 2) in_proj -> u / z   [2-product]
    hmma_gemm<0, 2048, 512, 2><<<dim3(8, ROWS / 128), 512, SM2>>>(
        xn_hi, xn_lo, win_hi, nullptr, nullptr, nullptr);

    // 3) local conv + SiLU -> uact (fp32 + fp16 hi)
    conv_local_x4<<<EWX4_BLOCKS, 256>>>(conv_lb);

    // 4) delta (fp16)   [1-product]
    hmma_gemm<1, 1024, 1024, 1><<<dim3(4, ROWS / 128), 512, SM1>>>(
        ua_hi, nullptr, wdt_hi, b_dt, nullptr, nullptr);

    // 5) Euler x4 (last writes h hi/lo)
    conv_diff_x4<false><<<EWX4_BLOCKS, 256>>>(uact, hA, alpha, beta_r);
    conv_diff_x4<false><<<EWX4_BLOCKS, 256>>>(hA,   hB, alpha, beta_r);
    conv_diff_x4<false><<<EWX4_BLOCKS, 256>>>(hB,   hA, alpha, beta_r);
    conv_diff_x4<true ><<<EWX4_BLOCKS, 256>>>(hA, nullptr, alpha, beta_r);

    // 6) g = (h@Wssm + u*D) * silu(z) -> g hi/lo   [2-product]
    hmma_gemm<2, 1024, 1024, 2><<<dim3(4, ROWS / 128), 512, SM2>>>(
        h_hi, h_lo, wssm_hi, D_param, nullptr, nullptr);

    // 7) out = g@Wout + residual   [2-product]
    hmma_gemm<3, 512, 1024, 2><<<dim3(2, ROWS / 128), 512, SM2>>>(
        gg_hi, gg_lo, wout_hi, nullptr, x, out);
}

// round 17
// speedup vs baseline: 1.0130x; 1.0057x over previous
#include <cuda_runtime.h>
#include <cuda_fp16.h>
#include <math.h>
#include <stdint.h>

#define D_MODEL 512
#define DI      1024
#define ROWS    32768

// ---------------- scratch (device globals) ----------------
__device__ __half g_xn_hi[ROWS * D_MODEL];
__device__ __half g_xn_lo[ROWS * D_MODEL];
__device__ float g_u    [ROWS * DI];
__device__ float g_z    [ROWS * DI];
__device__ float g_uact [ROWS * DI];
__device__ __half g_ua_hi[ROWS * DI];
__device__ __half g_delta[ROWS * DI];
__device__ float g_hA   [ROWS * DI];
__device__ float g_hB   [ROWS * DI];
__device__ __half g_h_hi[ROWS * DI];
__device__ __half g_h_lo[ROWS * DI];
__device__ __half g_g_hi[ROWS * DI];
__device__ __half g_g_lo[ROWS * DI];
// transposed weights: [N][K] fp16
__device__ __half g_win_hi [2048 * 512];
__device__ __half g_wdt_hi [1024 * 1024];
__device__ __half g_wssm_hi[1024 * 1024];
__device__ __half g_wout_hi[512 * 1024];
// conv weights transposed to [tap][channel]
__device__ float g_clw_t[9 * DI];
__device__ float g_cdw_t[9 * DI];

// ---------------- small helpers ----------------
__device__ __forceinline__ float siluf(float v) { return v / (1.0f + expf(-v)); }
__device__ __forceinline__ float softplus_clamp(float v) {
    float sp = (v > 15.0f) ? v : log1pf(expf(v));
    return fminf(sp, 0.15f);
}
__device__ __forceinline__ void split2h(float v, __half& hi, __half& lo) {
    hi = __float2half_rn(v);
    lo = __float2half_rn(v - __half2float(hi));
}

__device__ __forceinline__ void cpasync16(uint32_t dst, const void* src) {
    asm volatile("cp.async.cg.shared.global [%0], [%1], 16;" :: "r"(dst), "l"(src));
}
__device__ __forceinline__ void ldsm4(uint32_t a, uint32_t& r0, uint32_t& r1,
                                      uint32_t& r2, uint32_t& r3) {
    asm volatile("ldmatrix.sync.aligned.m8n8.x4.shared.b16 {%0,%1,%2,%3}, [%4];"
                 : "=r"(r0), "=r"(r1), "=r"(r2), "=r"(r3) : "r"(a));
}
__device__ __forceinline__ void mma16816h(float* c, const uint32_t* a,
                                          uint32_t b0, uint32_t b1) {
    asm volatile(
        "mma.sync.aligned.m16n8k16.row.col.f32.f16.f16.f32 "
        "{%0,%1,%2,%3}, {%4,%5,%6,%7}, {%8,%9}, {%0,%1,%2,%3};"
        : "+f"(c[0]), "+f"(c[1]), "+f"(c[2]), "+f"(c[3])
        : "r"(a[0]), "r"(a[1]), "r"(a[2]), "r"(a[3]), "r"(b0), "r"(b1));
}

// ---------------- LayerNorm -> fp16 hi/lo split ----------------
__global__ void __launch_bounds__(256) ln_kernel(const float* __restrict__ x,
                                                 const float* __restrict__ gamma,
                                                 const float* __restrict__ beta) {
    int row = blockIdx.x;
    const float* xr = x + (size_t)row * D_MODEL;
    int t = threadIdx.x;
    float v0 = xr[t], v1 = xr[t + 256];
    float s = v0 + v1, sq = v0 * v0 + v1 * v1;
    __shared__ float sh[32], shq[32];
    #pragma unroll
    for (int o = 16; o; o >>= 1) {
        s  += __shfl_down_sync(0xffffffffu, s,  o);
        sq += __shfl_down_sync(0xffffffffu, sq, o);
    }
    int lane = t & 31, w = t >> 5;
    if (lane == 0) { sh[w] = s; shq[w] = sq; }
    __syncthreads();
    if (t == 0) {
        float ts = 0.f, tq = 0.f;
        #pragma unroll
        for (int i = 0; i < 8; i++) { ts += sh[i]; tq += shq[i]; }
        float mu = ts * (1.0f / D_MODEL);
        float var = tq * (1.0f / D_MODEL) - mu * mu;
        sh[0] = mu;
        shq[0] = rsqrtf(var + 1e-5f);
    }
    __syncthreads();
    float mu = sh[0], rs = shq[0];
    size_t o = (size_t)row * D_MODEL;
    float a = (v0 - mu) * rs * gamma[t] + beta[t];
    float b = (v1 - mu) * rs * gamma[t + 256] + beta[t + 256];
    __half hi, lo;
    split2h(a, hi, lo); g_xn_hi[o + t] = hi;       g_xn_lo[o + t] = lo;
    split2h(b, hi, lo); g_xn_hi[o + t + 256] = hi; g_xn_lo[o + t + 256] = lo;
}

// ---------------- weight transpose (fp16 hi only) ----------------
__device__ __forceinline__ void wprep_tile(const float* __restrict__ W,
                                           __half* __restrict__ Thi,
                                           int K, int N, int tile) {
    __shared__ float t[32][33];
    int ntiles = N >> 5;
    int n0 = (tile % ntiles) * 32, k0 = (tile / ntiles) * 32;
    int tx = threadIdx.x & 31, ty = threadIdx.x >> 5;
    #pragma unroll
    for (int dy = 0; dy < 32; dy += 8)
        t[ty + dy][tx] = W[(size_t)(k0 + ty + dy) * N + n0 + tx];
    __syncthreads();
    #pragma unroll
    for (int dy = 0; dy < 32; dy += 8) {
        size_t o = (size_t)(n0 + ty + dy) * K + k0 + tx;
        Thi[o] = __float2half_rn(t[tx][ty + dy]);
    }
}

__global__ void __launch_bounds__(256) wprep2_kernel(
        const float* __restrict__ W0, __half* __restrict__ T0h,
        int K0, int N0, int ntile0,
        const float* __restrict__ W1, __half* __restrict__ T1h,
        int K1, int N1) {
    int b = blockIdx.x;
    if (b < ntile0) wprep_tile(W0, T0h, K0, N0, b);
    else            wprep_tile(W1, T1h, K1, N1, b - ntile0);
}

// ---------------- conv weight transpose: [C][9] -> [9][C] ----------------
__global__ void __launch_bounds__(256) convw_prep(const float* __restrict__ wl,
                                                  const float* __restrict__ wd) {
    int o = blockIdx.x * 256 + threadIdx.x;
    int which = o >= 9 * DI;
    int oo = which ? o - 9 * DI : o;
    int t = oo / DI, c = oo % DI;
    float v = (which ? wd : wl)[c * 9 + t];
    (which ? g_cdw_t : g_clw_t)[oo] = v;
}

// ---------------- HMMA fp16 GEMM, 128x256x32 tiles, 3-stage, 512 threads ----
// NPROD: 1 = ah*bh; 2 = ah*bh + al*bh
#define ASZ_   10240u
#define BSZ_   20480u

template<int K, int NPROD>
__device__ __forceinline__ void load_stage(uint32_t st, int tid,
        const __half* __restrict__ Ahi, const __half* __restrict__ Alo,
        const __half* __restrict__ Bhi,
        size_t arow, size_t brow, int chunk) {
    constexpr uint32_t AORG = (NPROD >= 2 ? 2u : 1u) * ASZ_;
    {
        int r = tid >> 2, cb = (tid & 3) * 16;
        uint32_t sa = st + (uint32_t)(r * 80 + cb);
        size_t ga = (arow + r) * (size_t)(K * 2) + chunk * 64 + cb;
        cpasync16(sa, (const char*)Ahi + ga);
        if (NPROD >= 2) cpasync16(sa + ASZ_, (const char*)Alo + ga);
    }
    #pragma unroll
    for (int i = 0; i < 2; i++) {
        int idx = tid + i * 512;
        int r = idx >> 2, cb = (idx & 3) * 16;
        uint32_t sbm = st + AORG + (uint32_t)(r * 80 + cb);
        size_t gb = (brow + r) * (size_t)(K * 2) + chunk * 64 + cb;
        cpasync16(sbm, (const char*)Bhi + gb);
    }
    asm volatile("cp.async.commit_group;");
}

// MODE 0: u half of in_proj -> g_u; MODE 4: z half -> g_z
// MODE 1: delta (fp16); MODE 2: g epilogue; MODE 3: out + residual
template<int MODE, int NOUT, int K, int NPROD>
__global__ void __launch_bounds__(512, 1)
hmma_gemm(const __half* __restrict__ Ahi, const __half* __restrict__ Alo,
          const __half* __restrict__ Bhi,
          const float* __restrict__ p0, const float* __restrict__ res,
          float* __restrict__ outp) {
    constexpr uint32_t AORG = (NPROD >= 2 ? 2u : 1u) * ASZ_;
    constexpr uint32_t STG  = AORG + BSZ_;
    extern __shared__ char smem_raw[];
    uint32_t sb = (uint32_t)__cvta_generic_to_shared(smem_raw);
    const int tid = threadIdx.x;
    const int lane = tid & 31, wid = tid >> 5;
    const int wm = wid & 3, wn = wid >> 2;           // 4m x 4n, warp tile 32x64
    const int bx = blockIdx.x, by = blockIdx.y;
    const size_t arow = (size_t)by * 128;
    const size_t brow = (size_t)bx * 256;
    constexpr int NC = K / 32;

    const int a_r = (lane & 7) + ((lane >> 3) & 1) * 8;
    const int a_c = ((lane >> 4) & 1) * 8;
    const int b_r = (lane & 7) + ((lane >> 4) & 1) * 8;
    const int b_c = ((lane >> 3) & 1) * 8;
    const uint32_t a_off = (uint32_t)((wm * 32 + a_r) * 80 + a_c * 2);
    const uint32_t b_off = AORG + (uint32_t)((wn * 64 + b_r) * 80 + b_c * 2);

    load_stage<K, NPROD>(sb,       tid, Ahi, Alo, Bhi, arow, brow, 0);
    load_stage<K, NPROD>(sb + STG, tid, Ahi, Alo, Bhi, arow, brow, 1);

    float acc[2][8][4];
    #pragma unroll
    for (int i = 0; i < 2; i++)
        #pragma unroll
        for (int j = 0; j < 8; j++)
            #pragma unroll
            for (int q = 0; q < 4; q++) acc[i][j][q] = 0.f;

    #pragma unroll 1
    for (int i = 0; i < NC; i++) {
        if (i + 1 < NC) asm volatile("cp.async.wait_group 1;");
        else            asm volatile("cp.async.wait_group 0;");
        __syncthreads();
        if (i + 2 < NC) {
            uint32_t stw = sb + (uint32_t)((i + 2) % 3) * STG;
            load_stage<K, NPROD>(stw, tid, Ahi, Alo, Bhi, arow, brow, i + 2);
        }
        uint32_t st = sb + (uint32_t)(i % 3) * STG;
        #pragma unroll
        for (int ks = 0; ks < 2; ks++) {
            uint32_t kb = (uint32_t)(ks * 32);
            uint32_t ah[2][4], al[2][4];
            #pragma unroll
            for (int mt = 0; mt < 2; mt++) {
                uint32_t a = st + a_off + (uint32_t)(mt * 16 * 80) + kb;
                ldsm4(a, ah[mt][0], ah[mt][1], ah[mt][2], ah[mt][3]);
                if (NPROD >= 2) ldsm4(a + ASZ_, al[mt][0], al[mt][1], al[mt][2], al[mt][3]);
            }
            #pragma unroll
            for (int np = 0; np < 4; np++) {
                uint32_t b = st + b_off + (uint32_t)(np * 16 * 80) + kb;
                uint32_t bh[4];
                ldsm4(b, bh[0], bh[1], bh[2], bh[3]);
                #pragma unroll
                for (int mt = 0; mt < 2; mt++) {
                    #pragma unroll
                    for (int hh = 0; hh < 2; hh++) {
                        float* c = acc[mt][np * 2 + hh];
                        mma16816h(c, ah[mt], bh[hh * 2], bh[hh * 2 + 1]);
                        if (NPROD >= 2)
                            mma16816h(c, al[mt], bh[hh * 2], bh[hh * 2 + 1]);
                    }
                }
            }
        }
    }

    // ---- epilogue ----
    const int quad = lane >> 2, qi = lane & 3;
    #pragma unroll
    for (int mt = 0; mt < 2; mt++) {
        #pragma unroll
        for (int nt = 0; nt < 8; nt++) {
            int r0 = by * 128 + wm * 32 + mt * 16 + quad;
            int c  = bx * 256 + wn * 64 + nt * 8 + qi * 2;
            float* a = acc[mt][nt];
            #pragma unroll
            for (int half = 0; half < 2; half++) {
                int row = r0 + half * 8;
                float v0 = a[half * 2], v1 = a[half * 2 + 1];
                if (MODE == 0) {
                    *(float2*)(g_u + (size_t)row * DI + c) = make_float2(v0, v1);
                } else if (MODE == 4) {
                    *(float2*)(g_z + (size_t)row * DI + c) = make_float2(v0, v1);
                } else if (MODE == 1) {
                    float2 bb = *(const float2*)(p0 + c);
                    __half2 d2 = __floats2half2_rn(softplus_clamp(v0 + bb.x),
                                                   softplus_clamp(v1 + bb.y));
                    *(__half2*)(g_delta + (size_t)row * DI + c) = d2;
                } else if (MODE == 2) {
                    size_t o = (size_t)row * DI + c;
                    float2 uu = *(const float2*)(g_uact + o);
                    float2 zz = *(const float2*)(g_z + o);
                    float2 dp = *(const float2*)(p0 + c);
                    float w0 = (v0 + uu.x * dp.x) * siluf(zz.x);
                    float w1 = (v1 + uu.y * dp.y) * siluf(zz.y);
                    __half h0, l0, h1, l1;
                    split2h(w0, h0, l0);
                    split2h(w1, h1, l1);
                    *(__half2*)(g_g_hi + o) = __half2(h0, h1);
                    *(__half2*)(g_g_lo + o) = __half2(l0, l1);
                } else {
                    size_t o = (size_t)row * (size_t)NOUT + c;
                    float2 rr = *(const float2*)(res + o);
                    *(float2*)(outp + o) = make_float2(v0 + rr.x, v1 + rr.y);
                }
            }
        }
    }
}

// ---------------- local conv (zero pad) + bias + SiLU, 4 x-pixels/thread ----
__global__ void __launch_bounds__(256) conv_local_x4(const float* __restrict__ bias) {
    int idx = blockIdx.x * 256 + threadIdx.x;          // over ROWS*DI/16
    int c4 = idx & 255;
    int unit = idx >> 8;                                // 8192 units
    int x0 = (unit & 15) * 4;
    int y  = (unit >> 4) & 63;
    int b  = unit >> 10;
    int c  = c4 * 4;

    float4 tv[3][6];
    #pragma unroll
    for (int ky = 0; ky < 3; ky++) {
        int yy = y + ky - 1;
        bool oky = (unsigned)yy < 64u;
        #pragma unroll
        for (int j = 0; j < 6; j++) {
            int xx = x0 + j - 1;
            bool ok = oky && ((unsigned)xx < 64u);
            int srow = (b << 12) | ((oky ? yy : 0) << 6) | (ok ? xx : 0);
            float4 v = *(const float4*)(g_u + (size_t)srow * DI + c);
            if (!ok) v = make_float4(0.f, 0.f, 0.f, 0.f);
            tv[ky][j] = v;
        }
    }
    float4 wt[9];
    #pragma unroll
    for (int t = 0; t < 9; t++) wt[t] = *(const float4*)(g_clw_t + t * DI + c);
    float4 bv = *(const float4*)(bias + c);

    #pragma unroll
    for (int px = 0; px < 4; px++) {
        float4 acc = bv;
        #pragma unroll
        for (int ky = 0; ky < 3; ky++)
            #pragma unroll
            for (int kx = 0; kx < 3; kx++) {
                float4 w = wt[ky * 3 + kx];
                float4 t = tv[ky][px + kx];
                acc.x = fmaf(w.x, t.x, acc.x);
                acc.y = fmaf(w.y, t.y, acc.y);
                acc.z = fmaf(w.z, t.z, acc.z);
                acc.w = fmaf(w.w, t.w, acc.w);
            }
        float4 v = make_float4(siluf(acc.x), siluf(acc.y), siluf(acc.z), siluf(acc.w));
        size_t o = ((size_t)((b << 12) | (y << 6) | (x0 + px))) * DI + c;
        *(float4*)(g_uact + o) = v;
        __half2 h01 = __floats2half2_rn(v.x, v.y);
        __half2 h23 = __floats2half2_rn(v.z, v.w);
        *(uint2*)(g_ua_hi + o) = make_uint2(*(uint32_t*)&h01, *(uint32_t*)&h23);
    }
}

// ---------------- diff conv (replicate pad) + Euler, 4 x-pixels/thread ----
template<bool LAST>
__global__ void __launch_bounds__(256) conv_diff_x4(const float* __restrict__ hin,
                                                    float* __restrict__ hout,
                                                    const float* __restrict__ alpha,
                                                    const float* __restrict__ beta) {
    int idx = blockIdx.x * 256 + threadIdx.x;
    int c4 = idx & 255;
    int unit = idx >> 8;
    int x0 = (unit & 15) * 4;
    int y  = (unit >> 4) & 63;
    int b  = unit >> 10;
    int c  = c4 * 4;

    float4 tv[3][6];
    #pragma unroll
    for (int ky = 0; ky < 3; ky++) {
        int yy = min(max(y + ky - 1, 0), 63);
        #pragma unroll
        for (int j = 0; j < 6; j++) {
            int xx = min(max(x0 + j - 1, 0), 63);
            int srow = (b << 12) | (yy << 6) | xx;
            tv[ky][j] = *(const float4*)(hin + (size_t)srow * DI + c);
        }
    }
    float4 wt[9];
    #pragma unroll
    for (int t = 0; t < 9; t++) wt[t] = *(const float4*)(g_cdw_t + t * DI + c);
    float4 al = *(const float4*)(alpha + c);
    float4 be = *(const float4*)(beta + c);

    #pragma unroll
    for (int px = 0; px < 4; px++) {
        float4 acc = make_float4(0.f, 0.f, 0.f, 0.f);
        #pragma unroll
        for (int ky = 0; ky < 3; ky++)
            #pragma unroll
            for (int kx = 0; kx < 3; kx++) {
                float4 w = wt[ky * 3 + kx];
                float4 t = tv[ky][px + kx];
                acc.x = fmaf(w.x, t.x, acc.x);
                acc.y = fmaf(w.y, t.y, acc.y);
                acc.z = fmaf(w.z, t.z, acc.z);
                acc.w = fmaf(w.w, t.w, acc.w);
            }
        size_t o = ((size_t)((b << 12) | (y << 6) | (x0 + px))) * DI + c;
        float4 h = tv[1][px + 1];
        uint2 draw = *(const uint2*)(g_delta + o);
        float2 d01 = __half22float2(*(__half2*)&draw.x);
        float2 d23 = __half22float2(*(__half2*)&draw.y);
        float4 v;
        v.x = h.x + 0.25f * (d01.x * acc.x + al.x * h.x - be.x * h.x * h.x * h.x);
        v.y = h.y + 0.25f * (d01.y * acc.y + al.y * h.y - be.y * h.y * h.y * h.y);
        v.z = h.z + 0.25f * (d23.x * acc.z + al.z * h.z - be.z * h.z * h.z * h.z);
        v.w = h.w + 0.25f * (d23.y * acc.w + al.w * h.w - be.w * h.w * h.w * h.w);
        if (LAST) {
            __half h0, l0, h1, l1, h2, l2, h3, l3;
            split2h(v.x, h0, l0); split2h(v.y, h1, l1);
            split2h(v.z, h2, l2); split2h(v.w, h3, l3);
            __half2 hh01(h0, h1), hh23(h2, h3), ll01(l0, l1), ll23(l2, l3);
            *(uint2*)(g_h_hi + o) = make_uint2(*(uint32_t*)&hh01, *(uint32_t*)&hh23);
            *(uint2*)(g_h_lo + o) = make_uint2(*(uint32_t*)&ll01, *(uint32_t*)&ll23);
        } else {
            *(float4*)(hout + o) = v;
        }
    }
}

extern "C" void kernel_launch(void* const* d_in, const int* in_sizes, int n_in,
                              void* d_out, int out_size) {
    const float* x         = (const float*)d_in[0];
    const float* ln_gamma  = (const float*)d_in[1];
    const float* ln_beta   = (const float*)d_in[2];
    const float* W_in      = (const float*)d_in[3];
    const float* conv_lw   = (const float*)d_in[4];
    const float* conv_lb   = (const float*)d_in[5];
    const float* W_dt      = (const float*)d_in[6];
    const float* b_dt      = (const float*)d_in[7];
    const float* D_param   = (const float*)d_in[8];
    const float* conv_dw   = (const float*)d_in[9];
    const float* alpha     = (const float*)d_in[10];
    const float* beta_r    = (const float*)d_in[11];
    const float* W_ssm_out = (const float*)d_in[12];
    const float* W_out     = (const float*)d_in[13];
    float* out             = (float*)d_out;

    __half *xn_hi, *xn_lo, *ua_hi, *h_hi, *h_lo, *gg_hi, *gg_lo;
    __half *win_hi, *wdt_hi, *wssm_hi, *wout_hi;
    float *hA, *hB, *uact;
    cudaGetSymbolAddress((void**)&xn_hi, g_xn_hi);
    cudaGetSymbolAddress((void**)&xn_lo, g_xn_lo);
    cudaGetSymbolAddress((void**)&ua_hi, g_ua_hi);
    cudaGetSymbolAddress((void**)&h_hi,  g_h_hi);
    cudaGetSymbolAddress((void**)&h_lo,  g_h_lo);
    cudaGetSymbolAddress((void**)&gg_hi, g_g_hi);
    cudaGetSymbolAddress((void**)&gg_lo, g_g_lo);
    cudaGetSymbolAddress((void**)&win_hi,  g_win_hi);
    cudaGetSymbolAddress((void**)&wdt_hi,  g_wdt_hi);
    cudaGetSymbolAddress((void**)&wssm_hi, g_wssm_hi);
    cudaGetSymbolAddress((void**)&wout_hi, g_wout_hi);
    cudaGetSymbolAddress((void**)&hA,   g_hA);
    cudaGetSymbolAddress((void**)&hB,   g_hB);
    cudaGetSymbolAddress((void**)&uact, g_uact);

    const int SM2 = 3 * (2 * 10240 + 20480);      // 122880 (2-prod)
    const int SM1 = 3 * (10240 + 20480);          // 92160  (1-prod)
    cudaFuncSetAttribute((const void*)hmma_gemm<0, 1024, 512,  2>,
                         cudaFuncAttributeMaxDynamicSharedMemorySize, SM2);
    cudaFuncSetAttribute((const void*)hmma_gemm<4, 1024, 512,  2>,
                         cudaFuncAttributeMaxDynamicSharedMemorySize, SM2);
    cudaFuncSetAttribute((const void*)hmma_gemm<1, 1024, 1024, 1>,
                         cudaFuncAttributeMaxDynamicSharedMemorySize, SM1);
    cudaFuncSetAttribute((const void*)hmma_gemm<2, 1024, 1024, 2>,
                         cudaFuncAttributeMaxDynamicSharedMemorySize, SM2);
    cudaFuncSetAttribute((const void*)hmma_gemm<3, 512,  1024, 2>,
                         cudaFuncAttributeMaxDynamicSharedMemorySize, SM2);

    const int EWX4_BLOCKS = (ROWS * DI / 16) / 256;   // 8192

    // side stream + fork/join events (host objects; created per call, capture-safe)
    cudaStream_t s2;
    cudaStreamCreateWithFlags(&s2, cudaStreamNonBlocking);
    cudaEvent_t evFork, evPrep, evFork2, evZ;
    cudaEventCreateWithFlags(&evFork,  cudaEventDisableTiming);
    cudaEventCreateWithFlags(&evPrep,  cudaEventDisableTiming);
    cudaEventCreateWithFlags(&evFork2, cudaEventDisableTiming);
    cudaEventCreateWithFlags(&evZ,     cudaEventDisableTiming);

    // fork s2: weight prep runs concurrently with LayerNorm
    cudaEventRecord(evFork, 0);
    cudaStreamWaitEvent(s2, evFork, 0);
    wprep2_kernel<<<2048, 256, 0, s2>>>(W_in, win_hi, 512, 2048, 1024,
                                        W_dt, wdt_hi, 1024, 1024);
    wprep2_kernel<<<1536, 256, 0, s2>>>(W_ssm_out, wssm_hi, 1024, 1024, 1024,
                                        W_out, wout_hi, 1024, 512);
    convw_prep<<<(2 * 9 * DI) / 256, 256, 0, s2>>>(conv_lw, conv_dw);
    cudaEventRecord(evPrep, s2);

    // 1) LayerNorm -> xn hi/lo (main stream)
    ln_kernel<<<ROWS, 256>>>(x, ln_gamma, ln_beta);

    // join: gemm0u needs xn + prepped weights
    cudaStreamWaitEvent(0, evPrep, 0);

    // 2a) in_proj u-half -> g_u [2-product] (critical path)
    hmma_gemm<0, 1024, 512, 2><<<dim3(4, ROWS / 128), 512, SM2>>>(
        xn_hi, xn_lo, win_hi, nullptr, nullptr, nullptr);

    // 2b) in_proj z-half -> g_z on s2, overlapped with conv/delta/Euler chain
    cudaEventRecord(evFork2, 0);
    cudaStreamWaitEvent(s2, evFork2, 0);
    hmma_gemm<4, 1024, 512, 2><<<dim3(4, ROWS / 128), 512, SM2, s2>>>(
        xn_hi, xn_lo, win_hi + (size_t)1024 * 512, nullptr, nullptr, nullptr);
    cudaEventRecord(evZ, s2);

    // 3) local conv + SiLU -> uact (fp32 + fp16 hi)
    conv_local_x4<<<EWX4_BLOCKS, 256>>>(conv_lb);

    // 4) delta (fp16)   [1-product]
    hmma_gemm<1, 1024, 1024, 1><<<dim3(4, ROWS / 128), 512, SM1>>>(
        ua_hi, nullptr, wdt_hi, b_dt, nullptr, nullptr);

    // 5) Euler x4 (last writes h hi/lo)
    conv_diff_x4<false><<<EWX4_BLOCKS, 256>>>(uact, hA, alpha, beta_r);
    conv_diff_x4<false><<<EWX4_BLOCKS, 256>>>(hA,   hB, alpha, beta_r);
    conv_diff_x4<false><<<EWX4_BLOCKS, 256>>>(hB,   hA, alpha, beta_r);
    conv_diff_x4<true ><<<EWX4_BLOCKS, 256>>>(hA, nullptr, alpha, beta_r);

    // join: gemm2 epilogue reads g_z
    cudaStreamWaitEvent(0, evZ, 0);

    // 6) g = (h@Wssm + u*D) * silu(z) -> g hi/lo   [2-product]
    hmma_gemm<2, 1024, 1024, 2><<<dim3(4, ROWS / 128), 512, SM2>>>(
        h_hi, h_lo, wssm_hi, D_param, nullptr, nullptr);

    // 7) out = g@Wout + residual   [2-product]
    hmma_gemm<3, 512, 1024, 2><<<dim3(2, ROWS / 128), 512, SM2>>>(
        gg_hi, gg_lo, wout_hi, nullptr, x, out);
}